// round 10
// baseline (speedup 1.0000x reference)
#include <cuda_runtime.h>
#include <cuda_bf16.h>
#include <cuda_fp16.h>
#include <math.h>
#include <stdint.h>

#define Bc 2
#define Sc 2048
#define Dc 2048
#define Hc 16
#define HDc 128
#define BQ 64
#define BK 128

// Scratch (allocation-free rule: __device__ globals)
__device__ float g_q[Bc*Sc*Dc];
__device__ float g_k[Bc*Sc*Dc];
__device__ float g_v[Bc*Sc*Dc];
__device__ float g_sc[2048*128];      // [pos][d]: sin at d, cos at 64+d
__device__ __half g_xh[Bc*Sc*Dc];     // activations fp16 hi
__device__ __half g_xl[Bc*Sc*Dc];     // activations fp16 lo (residual)
__device__ __half g_wh[4*Dc*Dc];      // weights fp16, transposed [N][K]
__device__ __half g_qh[Bc*Sc*Dc];     // Q fp16 hi (scaled, roped)
__device__ __half g_ql[Bc*Sc*Dc];     // Q fp16 lo
__device__ __half g_kh[Bc*Sc*Dc];     // K fp16 (single)
__device__ __half g_vth[Bc*Sc*Dc];    // V^T fp16: [b][h][hd][s]

// ---------------------------------------------------------------------------
// PTX helpers (baseline sm_80+ features only — target-portable)
// ---------------------------------------------------------------------------
__device__ __forceinline__ uint32_t smem_u32(const void* p) {
    uint32_t a;
    asm("{ .reg .u64 t; cvta.to.shared.u64 t, %1; cvt.u32.u64 %0, t; }" : "=r"(a) : "l"(p));
    return a;
}
__device__ __forceinline__ void cpasync16(uint32_t dst, const void* src) {
    asm volatile("cp.async.cg.shared.global [%0], [%1], 16;" :: "r"(dst), "l"(src));
}
__device__ __forceinline__ void cp_commit() {
    asm volatile("cp.async.commit_group;" ::: "memory");
}
template <int N>
__device__ __forceinline__ void cp_wait() {
    asm volatile("cp.async.wait_group %0;" :: "n"(N) : "memory");
}
__device__ __forceinline__ void ldsm4(uint32_t& r0, uint32_t& r1, uint32_t& r2,
                                      uint32_t& r3, uint32_t a) {
    asm volatile("ldmatrix.sync.aligned.m8n8.x4.shared.b16 {%0,%1,%2,%3}, [%4];"
                 : "=r"(r0), "=r"(r1), "=r"(r2), "=r"(r3) : "r"(a));
}
__device__ __forceinline__ void ldsm2(uint32_t& r0, uint32_t& r1, uint32_t a) {
    asm volatile("ldmatrix.sync.aligned.m8n8.x2.shared.b16 {%0,%1}, [%2];"
                 : "=r"(r0), "=r"(r1) : "r"(a));
}
__device__ __forceinline__ void mma16816h(float* d, const uint32_t* a, const uint32_t* b) {
    asm volatile(
        "mma.sync.aligned.m16n8k16.row.col.f32.f16.f16.f32 "
        "{%0,%1,%2,%3}, {%4,%5,%6,%7}, {%8,%9}, {%0,%1,%2,%3};"
        : "+f"(d[0]), "+f"(d[1]), "+f"(d[2]), "+f"(d[3])
        : "r"(a[0]), "r"(a[1]), "r"(a[2]), "r"(a[3]), "r"(b[0]), "r"(b[1]));
}
// split two floats into packed fp16x2 hi + lo parts
__device__ __forceinline__ void split2h(float a, float b, uint32_t& hi, uint32_t& lo) {
    __half ha = __float2half_rn(a), hb = __float2half_rn(b);
    __half la = __float2half_rn(a - __half2float(ha));
    __half lb = __float2half_rn(b - __half2float(hb));
    __half2 ph = __halves2half2(ha, hb);
    __half2 pl = __halves2half2(la, lb);
    hi = *reinterpret_cast<uint32_t*>(&ph);
    lo = *reinterpret_cast<uint32_t*>(&pl);
}
__device__ __forceinline__ uint32_t packh2(float a, float b) {
    __half2 t = __floats2half2_rn(a, b);
    return *reinterpret_cast<uint32_t*>(&t);
}
__device__ __forceinline__ float ex2(float x) {
    float y;
    asm("ex2.approx.ftz.f32 %0, %1;" : "=f"(y) : "f"(x));
    return y;
}

// ---------------------------------------------------------------------------
// HMMA fp16 2-pass GEMM: C = (Ah + Al) @ Wh, fp32 accum. grid.z selects
// weight slice and output. 3-stage cp.async pipeline, ONE barrier per k-tile:
// wait(tile i) -> sync -> issue load(tile i+2, into buffer last read at i-1,
// protected by this sync) -> compute tile i.
// ---------------------------------------------------------------------------
__global__ __launch_bounds__(256) void gemm_mma(
    const __half* __restrict__ Ahi, const __half* __restrict__ Alo,
    const __half* __restrict__ B0,
    float* __restrict__ c0, float* __restrict__ c1, float* __restrict__ c2)
{
    extern __shared__ __align__(1024) char sm_raw[];
    const uint32_t SMB = smem_u32(sm_raw);       // 3 stages x (A 16KB + B 16KB)

    const int z = blockIdx.z;
    const __half* Bh = B0 + (size_t)z * Dc * Dc;
    float* C = (z == 0) ? c0 : ((z == 1) ? c1 : c2);

    const int tid  = threadIdx.x;
    const int wid  = tid >> 5, lane = tid & 31;
    const int row0 = blockIdx.y * 128;
    const int col0 = blockIdx.x * 128;

    const int lr = tid >> 3;
    const int lc = tid & 7;
    uint32_t ldst[4];
    #pragma unroll
    for (int it = 0; it < 4; it++) {
        int r = lr + it * 32;
        ldst[it] = (uint32_t)r * 128u + (uint32_t)((lc ^ (r & 7)) << 4);
    }

    const int wm = (wid & 1) * 64;
    const int wn = (wid >> 1) * 32;
    const int arow = wm + (lane & 15);
    const int ahi  = lane >> 4;
    const int brow = wn + (lane & 7);
    const int bhi  = (lane >> 3) & 1;

    float acc[4][4][4];
    #pragma unroll
    for (int mf = 0; mf < 4; mf++)
        #pragma unroll
        for (int nf = 0; nf < 4; nf++)
            #pragma unroll
            for (int r = 0; r < 4; r++) acc[mf][nf][r] = 0.f;

    auto load_tile = [&](int i) {
        const int st = i % 3;
        const int s  = i >> 5;                 // 0: Ah, 1: Al
        const int kk = (i & 31) << 6;
        const __half* As = s ? Alo : Ahi;
        const uint32_t ab = SMB + st * 32768;
        const uint32_t bb = ab + 16384;
        #pragma unroll
        for (int it = 0; it < 4; it++) {
            int r = lr + it * 32;
            cpasync16(ab + ldst[it], As + (size_t)(row0 + r) * 2048 + kk + lc * 8);
            cpasync16(bb + ldst[it], Bh + (size_t)(col0 + r) * 2048 + kk + lc * 8);
        }
        cp_commit();
    };

    load_tile(0);
    load_tile(1);

    #pragma unroll 1
    for (int i = 0; i < 64; i++) {
        if (i + 1 < 64) cp_wait<1>();
        else            cp_wait<0>();
        __syncthreads();
        if (i + 2 < 64) load_tile(i + 2);

        const uint32_t ab = SMB + (i % 3) * 32768;
        const uint32_t bb = ab + 16384;

        #pragma unroll
        for (int ks = 0; ks < 4; ks++) {
            uint32_t afr[4][4], bfr[4][2];
            #pragma unroll
            for (int mf = 0; mf < 4; mf++) {
                int r = arow + mf * 16;
                uint32_t addr = ab + (uint32_t)r * 128u
                              + (uint32_t)(((ks * 2 + ahi) ^ (r & 7)) << 4);
                ldsm4(afr[mf][0], afr[mf][1], afr[mf][2], afr[mf][3], addr);
            }
            #pragma unroll
            for (int nf = 0; nf < 4; nf++) {
                int r = brow + nf * 8;
                uint32_t addr = bb + (uint32_t)r * 128u
                              + (uint32_t)(((ks * 2 + bhi) ^ (r & 7)) << 4);
                ldsm2(bfr[nf][0], bfr[nf][1], addr);
            }
            #pragma unroll
            for (int mf = 0; mf < 4; mf++)
                #pragma unroll
                for (int nf = 0; nf < 4; nf++)
                    mma16816h(acc[mf][nf], afr[mf], bfr[nf]);
        }
    }

    #pragma unroll
    for (int mf = 0; mf < 4; mf++) {
        int rA = row0 + wm + mf * 16 + (lane >> 2);
        #pragma unroll
        for (int nf = 0; nf < 4; nf++) {
            int cA = col0 + wn + nf * 8 + (lane & 3) * 2;
            float2 lo = make_float2(acc[mf][nf][0], acc[mf][nf][1]);
            float2 hi = make_float2(acc[mf][nf][2], acc[mf][nf][3]);
            *(float2*)(C + (size_t)rA * 2048 + cA)       = lo;
            *(float2*)(C + (size_t)(rA + 8) * 2048 + cA) = hi;
        }
    }
}

// ---------------------------------------------------------------------------
// fp32 -> (fp16 hi, fp16 lo) split (for X)
// ---------------------------------------------------------------------------
__global__ __launch_bounds__(256) void convert_split(
    const float* __restrict__ src, __half* __restrict__ hi,
    __half* __restrict__ lo, int n4)
{
    int idx = blockIdx.x * 256 + threadIdx.x;
    if (idx >= n4) return;
    float4 v = ((const float4*)src)[idx];
    uint32_t h0, l0, h1, l1;
    split2h(v.x, v.y, h0, l0);
    split2h(v.z, v.w, h1, l1);
    ((uint32_t*)hi)[2*idx]   = h0;
    ((uint32_t*)hi)[2*idx+1] = h1;
    ((uint32_t*)lo)[2*idx]   = l0;
    ((uint32_t*)lo)[2*idx+1] = l1;
}

// ---------------------------------------------------------------------------
// Weight transpose (all 4 weights in one launch via grid.z):
// W[K][N] fp32 -> Wh[N][K] fp16
// ---------------------------------------------------------------------------
__global__ __launch_bounds__(256) void convert_wt(
    const float* __restrict__ W0, const float* __restrict__ W1,
    const float* __restrict__ W2, const float* __restrict__ W3,
    __half* __restrict__ Wh)
{
    __shared__ float t[32][33];
    int tx = threadIdx.x, ty = threadIdx.y;
    int kb = blockIdx.y * 32, nb = blockIdx.x * 32;
    int z = blockIdx.z;
    const float* W = (z == 0) ? W0 : ((z == 1) ? W1 : ((z == 2) ? W2 : W3));
    __half* dst = Wh + (size_t)z * Dc * Dc;
    #pragma unroll
    for (int it = 0; it < 4; it++)
        t[ty + it * 8][tx] = W[(size_t)(kb + ty + it * 8) * 2048 + nb + tx];
    __syncthreads();
    #pragma unroll
    for (int it = 0; it < 4; it++) {
        float x = t[tx][ty + it * 8];
        dst[(size_t)(nb + ty + it * 8) * 2048 + kb + tx] = __float2half_rn(x);
    }
}

// ---------------------------------------------------------------------------
// sin/cos table: one entry per (pos, d) pair — the fp64 pow + sincosf
// transcendental work done ONCE (131k threads) instead of per (b,t,h,d).
// ---------------------------------------------------------------------------
__global__ __launch_bounds__(256) void sc_table()
{
    int idx = blockIdx.x * 256 + threadIdx.x;
    if (idx >= 2048 * 64) return;
    int d = idx & 63;
    int p = idx >> 6;
    double inv = 1.0 / pow(10000.0, (double)(2 * d) / 128.0);
    float f = (float)((double)p * inv);
    float sn, cs;
    sincosf(f, &sn, &cs);
    g_sc[p * 128 + d]      = sn;
    g_sc[p * 128 + 64 + d] = cs;
}

// ---------------------------------------------------------------------------
// RoPE (table-driven) + scale(Q by 1/sqrt(HD)*log2e) + fp16 split Q, fp16 K
// ---------------------------------------------------------------------------
__global__ __launch_bounds__(256) void rope_split(const int* __restrict__ pos_ids)
{
    int idx = blockIdx.x * 256 + threadIdx.x;
    if (idx >= Bc * Sc * Hc * 64) return;
    int d = idx & 63;
    int h = (idx >> 6) & (Hc - 1);
    int t = idx >> 10;

    int p = pos_ids[t];
    float sn = g_sc[p * 128 + d];
    float cs = g_sc[p * 128 + 64 + d];

    const float QS = 0.08838834764831845f * 1.4426950408889634f; // scale * log2(e)
    size_t base = (size_t)t * Dc + h * HDc + d;

    float q0 = g_q[base], q1 = g_q[base + 64];
    float r0 = (q0 * cs - q1 * sn) * QS;
    float r1 = (q1 * cs + q0 * sn) * QS;
    __half h0 = __float2half_rn(r0), h1 = __float2half_rn(r1);
    g_qh[base]      = h0;
    g_qh[base + 64] = h1;
    g_ql[base]      = __float2half_rn(r0 - __half2float(h0));
    g_ql[base + 64] = __float2half_rn(r1 - __half2float(h1));

    float k0 = g_k[base], k1 = g_k[base + 64];
    g_kh[base]      = __float2half_rn(k0 * cs - k1 * sn);
    g_kh[base + 64] = __float2half_rn(k1 * cs + k0 * sn);
}

// ---------------------------------------------------------------------------
// V transpose: g_v [b,s,h,hd] fp32 -> g_vth [b,h,hd,s] fp16
// ---------------------------------------------------------------------------
__global__ void vt_half()
{
    __shared__ float t[32][33];
    int tx = threadIdx.x, ty = threadIdx.y;
    int s0 = blockIdx.x * 32;
    int d0 = blockIdx.y * 32;
    int bh = blockIdx.z;
    int b = bh >> 4, h = bh & 15;
    #pragma unroll
    for (int it = 0; it < 4; it++)
        t[ty + it * 8][tx] =
            g_v[(size_t)(b * Sc + s0 + ty + it * 8) * Dc + h * HDc + d0 + tx];
    __syncthreads();
    #pragma unroll
    for (int it = 0; it < 4; it++) {
        float x = t[tx][ty + it * 8];
        size_t o = (size_t)((b * Hc + h) * HDc + d0 + ty + it * 8) * Sc + s0 + tx;
        g_vth[o] = __float2half_rn(x);
    }
}

// ---------------------------------------------------------------------------
// HMMA flash attention, causal. BQ=64 (4 warps), BK=128, 128 threads.
// QK: fp16 2-pass (Q split, K single). PV: fp16 single pass. f32 accum.
// Smem 96KB -> 2 CTAs/SM; cross-CTA overlap hides load latency.
// ---------------------------------------------------------------------------
__global__ __launch_bounds__(128) void flash_mma(const int* __restrict__ amask)
{
    extern __shared__ char fsm[];
    const uint32_t SMB = smem_u32(fsm);
    __shared__ int msk[BK];

    const int tid = threadIdx.x, wid = tid >> 5, lane = tid & 31;
    const int qb = gridDim.x - 1 - blockIdx.x;   // heavy tiles first
    const int h = blockIdx.y, b = blockIdx.z;

    const uint32_t QH = SMB;                     // 64 x 256B = 16KB
    const uint32_t QL = SMB + 16384;             // 16KB
    const uint32_t KB = SMB + 32768;             // 128 x 256B = 32KB
    const uint32_t VB = SMB + 65536;             // 128 x 256B = 32KB

    // ---- Q tiles (hi + lo fp16): 64 rows x 256B, swizzled ----
    {
        const size_t qoff = (size_t)(b * Sc + qb * BQ) * Dc + h * HDc;
        #pragma unroll
        for (int it = 0; it < 16; it++) {
            int idx = tid + it * 128;            // 0..2047
            int s = idx >> 10;
            int r = (idx >> 4) & 63;
            int u = idx & 15;
            const __half* src = (s ? g_ql : g_qh) + qoff + (size_t)r * Dc + u * 8;
            cpasync16(QH + s * 16384 + (uint32_t)r * 256 + (uint32_t)((u ^ (r & 7)) << 4), src);
        }
    }

    const int nk = (qb + 2) >> 1;                // ceil((qb+1)/2) BK=128 tiles

    auto load_kv = [&](int kb) {
        const size_t koff = (size_t)(b * Sc + kb * BK) * Dc + h * HDc;
        const size_t voff = (size_t)((b * Hc + h) * HDc) * Sc + kb * BK;
        #pragma unroll
        for (int it = 0; it < 16; it++) {        // K: 128 rows x 16 units
            int idx = tid + it * 128;
            int r = idx >> 4;
            int u = idx & 15;
            cpasync16(KB + (uint32_t)r * 256 + (uint32_t)((u ^ (r & 7)) << 4),
                      g_kh + koff + (size_t)r * Dc + u * 8);
        }
        #pragma unroll
        for (int it = 0; it < 16; it++) {        // V^T: 128 hd-rows x 256B (128 keys)
            int idx = tid + it * 128;
            int r = idx >> 4;
            int u = idx & 15;
            cpasync16(VB + (uint32_t)r * 256 + (uint32_t)((u ^ (r & 7)) << 4),
                      g_vth + voff + (size_t)r * Sc + u * 8);
        }
        msk[tid] = amask[b * Sc + kb * BK + tid];
    };

    float O[16][4];
    #pragma unroll
    for (int nh = 0; nh < 16; nh++)
        #pragma unroll
        for (int r = 0; r < 4; r++) O[nh][r] = 0.f;
    float m0 = -1e30f, m1 = -1e30f, l0 = 0.f, l1 = 0.f;

    const int wq = wid * 16;
    const int ar = wq + (lane & 15);
    const int ahalf = lane >> 4;
    const int brr   = (lane & 7) | ((lane & 16) >> 1);
    const int bhalf = (lane >> 3) & 1;
    const int row0g = qb * BQ + wq + (lane >> 2);

    #pragma unroll 1
    for (int kb = 0; kb < nk; kb++) {
        load_kv(kb);
        cp_commit();
        cp_wait<0>();                            // Q (first iter) + K/V complete
        __syncthreads();

        // ---- scores: Q K^T, fp16 2-pass ----
        float S[16][4];
        #pragma unroll
        for (int nf = 0; nf < 16; nf++)
            #pragma unroll
            for (int r = 0; r < 4; r++) S[nf][r] = 0.f;

        #pragma unroll
        for (int ks = 0; ks < 8; ks++) {
            uint32_t ah[4], al[4];
            uint32_t qu = (uint32_t)(((2 * ks + ahalf) ^ (ar & 7)) << 4);
            ldsm4(ah[0], ah[1], ah[2], ah[3], QH + (uint32_t)ar * 256 + qu);
            ldsm4(al[0], al[1], al[2], al[3], QL + (uint32_t)ar * 256 + qu);
            #pragma unroll
            for (int np = 0; np < 8; np++) {
                int r = np * 16 + brr;
                uint32_t uo = (uint32_t)(((2 * ks + bhalf) ^ (r & 7)) << 4);
                uint32_t bh[4];
                ldsm4(bh[0], bh[1], bh[2], bh[3], KB + (uint32_t)r * 256 + uo);
                mma16816h(S[2*np],     ah, bh + 0);
                mma16816h(S[2*np + 1], ah, bh + 2);
                mma16816h(S[2*np],     al, bh + 0);
                mma16816h(S[2*np + 1], al, bh + 2);
            }
        }

        // ---- mask (causal + padding) ----
        #pragma unroll
        for (int nf = 0; nf < 16; nf++) {
            int c0 = nf * 8 + (lane & 3) * 2;
            int g0 = kb * BK + c0;
            bool k0 = msk[c0] != 0;
            bool k1 = msk[c0 + 1] != 0;
            if (!k0 || g0     > row0g)     S[nf][0] = -1e30f;
            if (!k1 || g0 + 1 > row0g)     S[nf][1] = -1e30f;
            if (!k0 || g0     > row0g + 8) S[nf][2] = -1e30f;
            if (!k1 || g0 + 1 > row0g + 8) S[nf][3] = -1e30f;
        }

        // ---- online softmax (base-2; log2e folded into Q scale) ----
        float mr0 = -1e30f, mr1 = -1e30f;
        #pragma unroll
        for (int nf = 0; nf < 16; nf++) {
            mr0 = fmaxf(mr0, fmaxf(S[nf][0], S[nf][1]));
            mr1 = fmaxf(mr1, fmaxf(S[nf][2], S[nf][3]));
        }
        mr0 = fmaxf(mr0, __shfl_xor_sync(0xffffffffu, mr0, 1));
        mr0 = fmaxf(mr0, __shfl_xor_sync(0xffffffffu, mr0, 2));
        mr1 = fmaxf(mr1, __shfl_xor_sync(0xffffffffu, mr1, 1));
        mr1 = fmaxf(mr1, __shfl_xor_sync(0xffffffffu, mr1, 2));
        float mn0 = fmaxf(m0, mr0), mn1 = fmaxf(m1, mr1);
        float f0 = ex2(m0 - mn0), f1 = ex2(m1 - mn1);

        uint32_t PH[8][4];
        float rs0 = 0.f, rs1 = 0.f;
        #pragma unroll
        for (int nf = 0; nf < 16; nf++) {
            float p0 = ex2(S[nf][0] - mn0);
            float p1 = ex2(S[nf][1] - mn0);
            float p2 = ex2(S[nf][2] - mn1);
            float p3 = ex2(S[nf][3] - mn1);
            rs0 += p0 + p1;
            rs1 += p2 + p3;
            int kp = nf >> 1, hv = (nf & 1) * 2;
            PH[kp][hv]     = packh2(p0, p1);
            PH[kp][hv + 1] = packh2(p2, p3);
        }
        rs0 += __shfl_xor_sync(0xffffffffu, rs0, 1);
        rs0 += __shfl_xor_sync(0xffffffffu, rs0, 2);
        rs1 += __shfl_xor_sync(0xffffffffu, rs1, 1);
        rs1 += __shfl_xor_sync(0xffffffffu, rs1, 2);
        l0 = l0 * f0 + rs0;
        l1 = l1 * f1 + rs1;
        m0 = mn0; m1 = mn1;

        #pragma unroll
        for (int nh = 0; nh < 16; nh++) {
            O[nh][0] *= f0; O[nh][1] *= f0;
            O[nh][2] *= f1; O[nh][3] *= f1;
        }

        // ---- O += P V (fp16 single pass) ----
        #pragma unroll
        for (int kp = 0; kp < 8; kp++) {
            #pragma unroll
            for (int nhp = 0; nhp < 8; nhp++) {
                int r = nhp * 16 + brr;
                uint32_t uo = (uint32_t)(((2 * kp + bhalf) ^ (r & 7)) << 4);
                uint32_t vh[4];
                ldsm4(vh[0], vh[1], vh[2], vh[3], VB + (uint32_t)r * 256 + uo);
                mma16816h(O[2*nhp],     PH[kp], vh + 0);
                mma16816h(O[2*nhp + 1], PH[kp], vh + 2);
            }
        }
        __syncthreads();                         // protect K/V/msk for next tile
    }

    // ---- epilogue: normalize, fp16 split, write to xh/xl ----
    float i0 = 1.f / l0, i1 = 1.f / l1;
    size_t base0 = (size_t)(b * Sc + row0g) * Dc + h * HDc + (lane & 3) * 2;
    #pragma unroll
    for (int nh = 0; nh < 16; nh++) {
        uint32_t h0, lo0, h1, lo1;
        split2h(O[nh][0] * i0, O[nh][1] * i0, h0, lo0);
        split2h(O[nh][2] * i1, O[nh][3] * i1, h1, lo1);
        size_t a0 = base0 + nh * 8;
        size_t a1 = a0 + (size_t)8 * Dc;
        *(uint32_t*)(g_xh + a0) = h0;
        *(uint32_t*)(g_xl + a0) = lo0;
        *(uint32_t*)(g_xh + a1) = h1;
        *(uint32_t*)(g_xl + a1) = lo1;
    }
}

// ---------------------------------------------------------------------------
extern "C" void kernel_launch(void* const* d_in, const int* in_sizes, int n_in,
                              void* d_out, int out_size)
{
    const float* X   = (const float*)d_in[0];
    const int*   am  = (const int*)  d_in[1];
    const int*   pos = (const int*)  d_in[2];
    const float* Wq  = (const float*)d_in[3];
    const float* Wk  = (const float*)d_in[4];
    const float* Wv  = (const float*)d_in[5];
    const float* Wo  = (const float*)d_in[6];
    float* out = (float*)d_out;

    float *qp, *kp, *vp;
    __half *xh, *xl, *wh;
    cudaGetSymbolAddress((void**)&qp, g_q);
    cudaGetSymbolAddress((void**)&kp, g_k);
    cudaGetSymbolAddress((void**)&vp, g_v);
    cudaGetSymbolAddress((void**)&xh, g_xh);
    cudaGetSymbolAddress((void**)&xl, g_xl);
    cudaGetSymbolAddress((void**)&wh, g_wh);

    const size_t WSZ = (size_t)Dc * Dc;
    const int N4 = Bc * Sc * Dc / 4;

    sc_table<<<(2048 * 64) / 256, 256>>>();
    convert_split<<<(N4 + 255) / 256, 256>>>(X, xh, xl, N4);
    convert_wt<<<dim3(64, 64, 4), dim3(32, 8)>>>(Wq, Wk, Wv, Wo, wh);

    const int GEMM_SMEM = 98304;   // 3 stages x 32KB
    cudaFuncSetAttribute(gemm_mma, cudaFuncAttributeMaxDynamicSharedMemorySize, GEMM_SMEM);
    // fused QKV: grid.z selects weight + output
    gemm_mma<<<dim3(16, 32, 3), 256, GEMM_SMEM>>>(xh, xl, wh, qp, kp, vp);

    rope_split<<<(Bc * Sc * Hc * 64) / 256, 256>>>(pos);
    vt_half<<<dim3(64, 4, 32), dim3(32, 8)>>>();

    const int FLASH_SMEM = 98304;   // Q 32KB + K 32KB + V 32KB
    cudaFuncSetAttribute(flash_mma, cudaFuncAttributeMaxDynamicSharedMemorySize, FLASH_SMEM);
    flash_mma<<<dim3(Sc / BQ, Hc, Bc), 128, FLASH_SMEM>>>(am);

    // Wo projection
    gemm_mma<<<dim3(16, 32, 1), 256, GEMM_SMEM>>>(xh, xl, wh + 3 * WSZ, out, out, out);
}

// round 11
// speedup vs baseline: 1.0684x; 1.0684x over previous
#include <cuda_runtime.h>
#include <cuda_bf16.h>
#include <cuda_fp16.h>
#include <math.h>
#include <stdint.h>

#define Bc 2
#define Sc 2048
#define Dc 2048
#define Hc 16
#define HDc 128
#define BQ 64
#define BK 128

// Scratch (allocation-free rule: __device__ globals)
__device__ float g_q[Bc*Sc*Dc];
__device__ float g_k[Bc*Sc*Dc];
__device__ float g_v[Bc*Sc*Dc];
__device__ float g_sc[2048*128];      // [pos][d]: sin at d, cos at 64+d
__device__ __half g_xh[Bc*Sc*Dc];     // activations fp16 hi
__device__ __half g_xl[Bc*Sc*Dc];     // activations fp16 lo (residual)
__device__ __half g_wh[4*Dc*Dc];      // weights fp16, transposed [N][K]
__device__ __half g_qh[Bc*Sc*Dc];     // Q fp16 hi (scaled, roped)
__device__ __half g_ql[Bc*Sc*Dc];     // Q fp16 lo
__device__ __half g_kh[Bc*Sc*Dc];     // K fp16 (single)
__device__ __half g_vth[Bc*Sc*Dc];    // V^T fp16: [b][h][hd][s]

// ---------------------------------------------------------------------------
// PTX helpers (baseline sm_80+ features only — target-portable)
// ---------------------------------------------------------------------------
__device__ __forceinline__ uint32_t smem_u32(const void* p) {
    uint32_t a;
    asm("{ .reg .u64 t; cvta.to.shared.u64 t, %1; cvt.u32.u64 %0, t; }" : "=r"(a) : "l"(p));
    return a;
}
__device__ __forceinline__ void cpasync16(uint32_t dst, const void* src) {
    asm volatile("cp.async.cg.shared.global [%0], [%1], 16;" :: "r"(dst), "l"(src));
}
__device__ __forceinline__ void cp_commit() {
    asm volatile("cp.async.commit_group;" ::: "memory");
}
template <int N>
__device__ __forceinline__ void cp_wait() {
    asm volatile("cp.async.wait_group %0;" :: "n"(N) : "memory");
}
__device__ __forceinline__ void ldsm4(uint32_t& r0, uint32_t& r1, uint32_t& r2,
                                      uint32_t& r3, uint32_t a) {
    asm volatile("ldmatrix.sync.aligned.m8n8.x4.shared.b16 {%0,%1,%2,%3}, [%4];"
                 : "=r"(r0), "=r"(r1), "=r"(r2), "=r"(r3) : "r"(a));
}
__device__ __forceinline__ void ldsm2(uint32_t& r0, uint32_t& r1, uint32_t a) {
    asm volatile("ldmatrix.sync.aligned.m8n8.x2.shared.b16 {%0,%1}, [%2];"
                 : "=r"(r0), "=r"(r1) : "r"(a));
}
__device__ __forceinline__ void mma16816h(float* d, const uint32_t* a, const uint32_t* b) {
    asm volatile(
        "mma.sync.aligned.m16n8k16.row.col.f32.f16.f16.f32 "
        "{%0,%1,%2,%3}, {%4,%5,%6,%7}, {%8,%9}, {%0,%1,%2,%3};"
        : "+f"(d[0]), "+f"(d[1]), "+f"(d[2]), "+f"(d[3])
        : "r"(a[0]), "r"(a[1]), "r"(a[2]), "r"(a[3]), "r"(b[0]), "r"(b[1]));
}
// split two floats into packed fp16x2 hi + lo parts
__device__ __forceinline__ void split2h(float a, float b, uint32_t& hi, uint32_t& lo) {
    __half ha = __float2half_rn(a), hb = __float2half_rn(b);
    __half la = __float2half_rn(a - __half2float(ha));
    __half lb = __float2half_rn(b - __half2float(hb));
    __half2 ph = __halves2half2(ha, hb);
    __half2 pl = __halves2half2(la, lb);
    hi = *reinterpret_cast<uint32_t*>(&ph);
    lo = *reinterpret_cast<uint32_t*>(&pl);
}
__device__ __forceinline__ uint32_t packh2(float a, float b) {
    __half2 t = __floats2half2_rn(a, b);
    return *reinterpret_cast<uint32_t*>(&t);
}
__device__ __forceinline__ float ex2(float x) {
    float y;
    asm("ex2.approx.ftz.f32 %0, %1;" : "=f"(y) : "f"(x));
    return y;
}

// ---------------------------------------------------------------------------
// HMMA fp16 2-pass GEMM with B-register-reuse: each k-tile stage holds
// Ah + Al + B; B fragments are loaded once per ks-step and used for BOTH
// the Ah and Al MMA batches (halves B smem reads + B gmem traffic).
// 32 combined k-tiles, 2-stage cp.async double buffer (R9 skeleton).
// ---------------------------------------------------------------------------
__global__ __launch_bounds__(256) void gemm_mma(
    const __half* __restrict__ Ahi, const __half* __restrict__ Alo,
    const __half* __restrict__ B0,
    float* __restrict__ c0, float* __restrict__ c1, float* __restrict__ c2)
{
    extern __shared__ __align__(1024) char sm_raw[];
    const uint32_t SMB = smem_u32(sm_raw);       // 2 stages x (Ah 16K + Al 16K + B 16K)

    const int z = blockIdx.z;
    const __half* Bh = B0 + (size_t)z * Dc * Dc;
    float* C = (z == 0) ? c0 : ((z == 1) ? c1 : c2);

    const int tid  = threadIdx.x;
    const int wid  = tid >> 5, lane = tid & 31;
    const int row0 = blockIdx.y * 128;
    const int col0 = blockIdx.x * 128;

    const int lr = tid >> 3;
    const int lc = tid & 7;
    uint32_t ldst[4];
    #pragma unroll
    for (int it = 0; it < 4; it++) {
        int r = lr + it * 32;
        ldst[it] = (uint32_t)r * 128u + (uint32_t)((lc ^ (r & 7)) << 4);
    }

    const int wm = (wid & 1) * 64;
    const int wn = (wid >> 1) * 32;
    const int arow = wm + (lane & 15);
    const int ahi  = lane >> 4;
    const int brow = wn + (lane & 7);
    const int bhi  = (lane >> 3) & 1;

    float acc[4][4][4];
    #pragma unroll
    for (int mf = 0; mf < 4; mf++)
        #pragma unroll
        for (int nf = 0; nf < 4; nf++)
            #pragma unroll
            for (int r = 0; r < 4; r++) acc[mf][nf][r] = 0.f;

    auto load_tile = [&](int i) {
        const int st = i & 1;
        const int kk = i << 6;
        const uint32_t ah = SMB + st * 49152;
        const uint32_t al = ah + 16384;
        const uint32_t bb = ah + 32768;
        #pragma unroll
        for (int it = 0; it < 4; it++) {
            int r = lr + it * 32;
            const size_t go = (size_t)(row0 + r) * 2048 + kk + lc * 8;
            cpasync16(ah + ldst[it], Ahi + go);
            cpasync16(al + ldst[it], Alo + go);
            cpasync16(bb + ldst[it], Bh + (size_t)(col0 + r) * 2048 + kk + lc * 8);
        }
        cp_commit();
    };

    load_tile(0);

    #pragma unroll 1
    for (int i = 0; i < 32; i++) {
        if (i + 1 < 32) { load_tile(i + 1); cp_wait<1>(); }
        else            { cp_wait<0>(); }
        __syncthreads();

        const uint32_t ah_b = SMB + (i & 1) * 49152;
        const uint32_t al_b = ah_b + 16384;
        const uint32_t bb   = ah_b + 32768;

        #pragma unroll
        for (int ks = 0; ks < 4; ks++) {
            uint32_t bfr[4][2];
            #pragma unroll
            for (int nf = 0; nf < 4; nf++) {
                int r = brow + nf * 8;
                uint32_t addr = bb + (uint32_t)r * 128u
                              + (uint32_t)(((ks * 2 + bhi) ^ (r & 7)) << 4);
                ldsm2(bfr[nf][0], bfr[nf][1], addr);
            }
            uint32_t afr[4][4];
            #pragma unroll
            for (int mf = 0; mf < 4; mf++) {
                int r = arow + mf * 16;
                uint32_t au = (uint32_t)r * 128u
                            + (uint32_t)(((ks * 2 + ahi) ^ (r & 7)) << 4);
                ldsm4(afr[mf][0], afr[mf][1], afr[mf][2], afr[mf][3], ah_b + au);
            }
            #pragma unroll
            for (int mf = 0; mf < 4; mf++)
                #pragma unroll
                for (int nf = 0; nf < 4; nf++)
                    mma16816h(acc[mf][nf], afr[mf], bfr[nf]);
            // Al pass reuses bfr in registers
            #pragma unroll
            for (int mf = 0; mf < 4; mf++) {
                int r = arow + mf * 16;
                uint32_t au = (uint32_t)r * 128u
                            + (uint32_t)(((ks * 2 + ahi) ^ (r & 7)) << 4);
                ldsm4(afr[mf][0], afr[mf][1], afr[mf][2], afr[mf][3], al_b + au);
            }
            #pragma unroll
            for (int mf = 0; mf < 4; mf++)
                #pragma unroll
                for (int nf = 0; nf < 4; nf++)
                    mma16816h(acc[mf][nf], afr[mf], bfr[nf]);
        }
        __syncthreads();
    }

    #pragma unroll
    for (int mf = 0; mf < 4; mf++) {
        int rA = row0 + wm + mf * 16 + (lane >> 2);
        #pragma unroll
        for (int nf = 0; nf < 4; nf++) {
            int cA = col0 + wn + nf * 8 + (lane & 3) * 2;
            float2 lo = make_float2(acc[mf][nf][0], acc[mf][nf][1]);
            float2 hi = make_float2(acc[mf][nf][2], acc[mf][nf][3]);
            *(float2*)(C + (size_t)rA * 2048 + cA)       = lo;
            *(float2*)(C + (size_t)(rA + 8) * 2048 + cA) = hi;
        }
    }
}

// ---------------------------------------------------------------------------
// fp32 -> (fp16 hi, fp16 lo) split (for X)
// ---------------------------------------------------------------------------
__global__ __launch_bounds__(256) void convert_split(
    const float* __restrict__ src, __half* __restrict__ hi,
    __half* __restrict__ lo, int n4)
{
    int idx = blockIdx.x * 256 + threadIdx.x;
    if (idx >= n4) return;
    float4 v = ((const float4*)src)[idx];
    uint32_t h0, l0, h1, l1;
    split2h(v.x, v.y, h0, l0);
    split2h(v.z, v.w, h1, l1);
    ((uint32_t*)hi)[2*idx]   = h0;
    ((uint32_t*)hi)[2*idx+1] = h1;
    ((uint32_t*)lo)[2*idx]   = l0;
    ((uint32_t*)lo)[2*idx+1] = l1;
}

// ---------------------------------------------------------------------------
// Weight transpose (all 4 weights in one launch via grid.z):
// W[K][N] fp32 -> Wh[N][K] fp16
// ---------------------------------------------------------------------------
__global__ __launch_bounds__(256) void convert_wt(
    const float* __restrict__ W0, const float* __restrict__ W1,
    const float* __restrict__ W2, const float* __restrict__ W3,
    __half* __restrict__ Wh)
{
    __shared__ float t[32][33];
    int tx = threadIdx.x, ty = threadIdx.y;
    int kb = blockIdx.y * 32, nb = blockIdx.x * 32;
    int z = blockIdx.z;
    const float* W = (z == 0) ? W0 : ((z == 1) ? W1 : ((z == 2) ? W2 : W3));
    __half* dst = Wh + (size_t)z * Dc * Dc;
    #pragma unroll
    for (int it = 0; it < 4; it++)
        t[ty + it * 8][tx] = W[(size_t)(kb + ty + it * 8) * 2048 + nb + tx];
    __syncthreads();
    #pragma unroll
    for (int it = 0; it < 4; it++) {
        float x = t[tx][ty + it * 8];
        dst[(size_t)(nb + ty + it * 8) * 2048 + kb + tx] = __float2half_rn(x);
    }
}

// ---------------------------------------------------------------------------
// sin/cos table: transcendental work once per (pos, d) pair
// ---------------------------------------------------------------------------
__global__ __launch_bounds__(256) void sc_table()
{
    int idx = blockIdx.x * 256 + threadIdx.x;
    if (idx >= 2048 * 64) return;
    int d = idx & 63;
    int p = idx >> 6;
    double inv = 1.0 / pow(10000.0, (double)(2 * d) / 128.0);
    float f = (float)((double)p * inv);
    float sn, cs;
    sincosf(f, &sn, &cs);
    g_sc[p * 128 + d]      = sn;
    g_sc[p * 128 + 64 + d] = cs;
}

// ---------------------------------------------------------------------------
// RoPE (table-driven) + scale(Q by 1/sqrt(HD)*log2e) + fp16 split Q, fp16 K
// ---------------------------------------------------------------------------
__global__ __launch_bounds__(256) void rope_split(const int* __restrict__ pos_ids)
{
    int idx = blockIdx.x * 256 + threadIdx.x;
    if (idx >= Bc * Sc * Hc * 64) return;
    int d = idx & 63;
    int h = (idx >> 6) & (Hc - 1);
    int t = idx >> 10;

    int p = pos_ids[t];
    float sn = g_sc[p * 128 + d];
    float cs = g_sc[p * 128 + 64 + d];

    const float QS = 0.08838834764831845f * 1.4426950408889634f; // scale * log2(e)
    size_t base = (size_t)t * Dc + h * HDc + d;

    float q0 = g_q[base], q1 = g_q[base + 64];
    float r0 = (q0 * cs - q1 * sn) * QS;
    float r1 = (q1 * cs + q0 * sn) * QS;
    __half h0 = __float2half_rn(r0), h1 = __float2half_rn(r1);
    g_qh[base]      = h0;
    g_qh[base + 64] = h1;
    g_ql[base]      = __float2half_rn(r0 - __half2float(h0));
    g_ql[base + 64] = __float2half_rn(r1 - __half2float(h1));

    float k0 = g_k[base], k1 = g_k[base + 64];
    g_kh[base]      = __float2half_rn(k0 * cs - k1 * sn);
    g_kh[base + 64] = __float2half_rn(k1 * cs + k0 * sn);
}

// ---------------------------------------------------------------------------
// V transpose: g_v [b,s,h,hd] fp32 -> g_vth [b,h,hd,s] fp16
// ---------------------------------------------------------------------------
__global__ void vt_half()
{
    __shared__ float t[32][33];
    int tx = threadIdx.x, ty = threadIdx.y;
    int s0 = blockIdx.x * 32;
    int d0 = blockIdx.y * 32;
    int bh = blockIdx.z;
    int b = bh >> 4, h = bh & 15;
    #pragma unroll
    for (int it = 0; it < 4; it++)
        t[ty + it * 8][tx] =
            g_v[(size_t)(b * Sc + s0 + ty + it * 8) * Dc + h * HDc + d0 + tx];
    __syncthreads();
    #pragma unroll
    for (int it = 0; it < 4; it++) {
        float x = t[tx][ty + it * 8];
        size_t o = (size_t)((b * Hc + h) * HDc + d0 + ty + it * 8) * Sc + s0 + tx;
        g_vth[o] = __float2half_rn(x);
    }
}

// ---------------------------------------------------------------------------
// HMMA flash attention, causal. BQ=64 (4 warps), BK=128, 128 threads.
// QK: fp16 2-pass (Q split, K single). PV: fp16 single pass. f32 accum.
// Smem 96KB -> 2 CTAs/SM; cross-CTA overlap hides load latency.
// ---------------------------------------------------------------------------
__global__ __launch_bounds__(128) void flash_mma(const int* __restrict__ amask)
{
    extern __shared__ char fsm[];
    const uint32_t SMB = smem_u32(fsm);
    __shared__ int msk[BK];

    const int tid = threadIdx.x, wid = tid >> 5, lane = tid & 31;
    const int qb = gridDim.x - 1 - blockIdx.x;   // heavy tiles first
    const int h = blockIdx.y, b = blockIdx.z;

    const uint32_t QH = SMB;                     // 64 x 256B = 16KB
    const uint32_t QL = SMB + 16384;             // 16KB
    const uint32_t KB = SMB + 32768;             // 128 x 256B = 32KB
    const uint32_t VB = SMB + 65536;             // 128 x 256B = 32KB

    // ---- Q tiles (hi + lo fp16): 64 rows x 256B, swizzled ----
    {
        const size_t qoff = (size_t)(b * Sc + qb * BQ) * Dc + h * HDc;
        #pragma unroll
        for (int it = 0; it < 16; it++) {
            int idx = tid + it * 128;            // 0..2047
            int s = idx >> 10;
            int r = (idx >> 4) & 63;
            int u = idx & 15;
            const __half* src = (s ? g_ql : g_qh) + qoff + (size_t)r * Dc + u * 8;
            cpasync16(QH + s * 16384 + (uint32_t)r * 256 + (uint32_t)((u ^ (r & 7)) << 4), src);
        }
    }

    const int nk = (qb + 2) >> 1;                // ceil((qb+1)/2) BK=128 tiles

    auto load_kv = [&](int kb) {
        const size_t koff = (size_t)(b * Sc + kb * BK) * Dc + h * HDc;
        const size_t voff = (size_t)((b * Hc + h) * HDc) * Sc + kb * BK;
        #pragma unroll
        for (int it = 0; it < 16; it++) {        // K: 128 rows x 16 units
            int idx = tid + it * 128;
            int r = idx >> 4;
            int u = idx & 15;
            cpasync16(KB + (uint32_t)r * 256 + (uint32_t)((u ^ (r & 7)) << 4),
                      g_kh + koff + (size_t)r * Dc + u * 8);
        }
        #pragma unroll
        for (int it = 0; it < 16; it++) {        // V^T: 128 hd-rows x 256B (128 keys)
            int idx = tid + it * 128;
            int r = idx >> 4;
            int u = idx & 15;
            cpasync16(VB + (uint32_t)r * 256 + (uint32_t)((u ^ (r & 7)) << 4),
                      g_vth + voff + (size_t)r * Sc + u * 8);
        }
        msk[tid] = amask[b * Sc + kb * BK + tid];
    };

    float O[16][4];
    #pragma unroll
    for (int nh = 0; nh < 16; nh++)
        #pragma unroll
        for (int r = 0; r < 4; r++) O[nh][r] = 0.f;
    float m0 = -1e30f, m1 = -1e30f, l0 = 0.f, l1 = 0.f;

    const int wq = wid * 16;
    const int ar = wq + (lane & 15);
    const int ahalf = lane >> 4;
    const int brr   = (lane & 7) | ((lane & 16) >> 1);
    const int bhalf = (lane >> 3) & 1;
    const int row0g = qb * BQ + wq + (lane >> 2);

    #pragma unroll 1
    for (int kb = 0; kb < nk; kb++) {
        load_kv(kb);
        cp_commit();
        cp_wait<0>();                            // Q (first iter) + K/V complete
        __syncthreads();

        // ---- scores: Q K^T, fp16 2-pass ----
        float S[16][4];
        #pragma unroll
        for (int nf = 0; nf < 16; nf++)
            #pragma unroll
            for (int r = 0; r < 4; r++) S[nf][r] = 0.f;

        #pragma unroll
        for (int ks = 0; ks < 8; ks++) {
            uint32_t ah[4], al[4];
            uint32_t qu = (uint32_t)(((2 * ks + ahalf) ^ (ar & 7)) << 4);
            ldsm4(ah[0], ah[1], ah[2], ah[3], QH + (uint32_t)ar * 256 + qu);
            ldsm4(al[0], al[1], al[2], al[3], QL + (uint32_t)ar * 256 + qu);
            #pragma unroll
            for (int np = 0; np < 8; np++) {
                int r = np * 16 + brr;
                uint32_t uo = (uint32_t)(((2 * ks + bhalf) ^ (r & 7)) << 4);
                uint32_t bh[4];
                ldsm4(bh[0], bh[1], bh[2], bh[3], KB + (uint32_t)r * 256 + uo);
                mma16816h(S[2*np],     ah, bh + 0);
                mma16816h(S[2*np + 1], ah, bh + 2);
                mma16816h(S[2*np],     al, bh + 0);
                mma16816h(S[2*np + 1], al, bh + 2);
            }
        }

        // ---- mask (causal + padding) ----
        #pragma unroll
        for (int nf = 0; nf < 16; nf++) {
            int c0 = nf * 8 + (lane & 3) * 2;
            int g0 = kb * BK + c0;
            bool k0 = msk[c0] != 0;
            bool k1 = msk[c0 + 1] != 0;
            if (!k0 || g0     > row0g)     S[nf][0] = -1e30f;
            if (!k1 || g0 + 1 > row0g)     S[nf][1] = -1e30f;
            if (!k0 || g0     > row0g + 8) S[nf][2] = -1e30f;
            if (!k1 || g0 + 1 > row0g + 8) S[nf][3] = -1e30f;
        }

        // ---- online softmax (base-2; log2e folded into Q scale) ----
        float mr0 = -1e30f, mr1 = -1e30f;
        #pragma unroll
        for (int nf = 0; nf < 16; nf++) {
            mr0 = fmaxf(mr0, fmaxf(S[nf][0], S[nf][1]));
            mr1 = fmaxf(mr1, fmaxf(S[nf][2], S[nf][3]));
        }
        mr0 = fmaxf(mr0, __shfl_xor_sync(0xffffffffu, mr0, 1));
        mr0 = fmaxf(mr0, __shfl_xor_sync(0xffffffffu, mr0, 2));
        mr1 = fmaxf(mr1, __shfl_xor_sync(0xffffffffu, mr1, 1));
        mr1 = fmaxf(mr1, __shfl_xor_sync(0xffffffffu, mr1, 2));
        float mn0 = fmaxf(m0, mr0), mn1 = fmaxf(m1, mr1);
        float f0 = ex2(m0 - mn0), f1 = ex2(m1 - mn1);

        uint32_t PH[8][4];
        float rs0 = 0.f, rs1 = 0.f;
        #pragma unroll
        for (int nf = 0; nf < 16; nf++) {
            float p0 = ex2(S[nf][0] - mn0);
            float p1 = ex2(S[nf][1] - mn0);
            float p2 = ex2(S[nf][2] - mn1);
            float p3 = ex2(S[nf][3] - mn1);
            rs0 += p0 + p1;
            rs1 += p2 + p3;
            int kp = nf >> 1, hv = (nf & 1) * 2;
            PH[kp][hv]     = packh2(p0, p1);
            PH[kp][hv + 1] = packh2(p2, p3);
        }
        rs0 += __shfl_xor_sync(0xffffffffu, rs0, 1);
        rs0 += __shfl_xor_sync(0xffffffffu, rs0, 2);
        rs1 += __shfl_xor_sync(0xffffffffu, rs1, 1);
        rs1 += __shfl_xor_sync(0xffffffffu, rs1, 2);
        l0 = l0 * f0 + rs0;
        l1 = l1 * f1 + rs1;
        m0 = mn0; m1 = mn1;

        #pragma unroll
        for (int nh = 0; nh < 16; nh++) {
            O[nh][0] *= f0; O[nh][1] *= f0;
            O[nh][2] *= f1; O[nh][3] *= f1;
        }

        // ---- O += P V (fp16 single pass) ----
        #pragma unroll
        for (int kp = 0; kp < 8; kp++) {
            #pragma unroll
            for (int nhp = 0; nhp < 8; nhp++) {
                int r = nhp * 16 + brr;
                uint32_t uo = (uint32_t)(((2 * kp + bhalf) ^ (r & 7)) << 4);
                uint32_t vh[4];
                ldsm4(vh[0], vh[1], vh[2], vh[3], VB + (uint32_t)r * 256 + uo);
                mma16816h(O[2*nhp],     PH[kp], vh + 0);
                mma16816h(O[2*nhp + 1], PH[kp], vh + 2);
            }
        }
        __syncthreads();                         // protect K/V/msk for next tile
    }

    // ---- epilogue: normalize, fp16 split, write to xh/xl ----
    float i0 = 1.f / l0, i1 = 1.f / l1;
    size_t base0 = (size_t)(b * Sc + row0g) * Dc + h * HDc + (lane & 3) * 2;
    #pragma unroll
    for (int nh = 0; nh < 16; nh++) {
        uint32_t h0, lo0, h1, lo1;
        split2h(O[nh][0] * i0, O[nh][1] * i0, h0, lo0);
        split2h(O[nh][2] * i1, O[nh][3] * i1, h1, lo1);
        size_t a0 = base0 + nh * 8;
        size_t a1 = a0 + (size_t)8 * Dc;
        *(uint32_t*)(g_xh + a0) = h0;
        *(uint32_t*)(g_xl + a0) = lo0;
        *(uint32_t*)(g_xh + a1) = h1;
        *(uint32_t*)(g_xl + a1) = lo1;
    }
}

// ---------------------------------------------------------------------------
extern "C" void kernel_launch(void* const* d_in, const int* in_sizes, int n_in,
                              void* d_out, int out_size)
{
    const float* X   = (const float*)d_in[0];
    const int*   am  = (const int*)  d_in[1];
    const int*   pos = (const int*)  d_in[2];
    const float* Wq  = (const float*)d_in[3];
    const float* Wk  = (const float*)d_in[4];
    const float* Wv  = (const float*)d_in[5];
    const float* Wo  = (const float*)d_in[6];
    float* out = (float*)d_out;

    float *qp, *kp, *vp;
    __half *xh, *xl, *wh;
    cudaGetSymbolAddress((void**)&qp, g_q);
    cudaGetSymbolAddress((void**)&kp, g_k);
    cudaGetSymbolAddress((void**)&vp, g_v);
    cudaGetSymbolAddress((void**)&xh, g_xh);
    cudaGetSymbolAddress((void**)&xl, g_xl);
    cudaGetSymbolAddress((void**)&wh, g_wh);

    const size_t WSZ = (size_t)Dc * Dc;
    const int N4 = Bc * Sc * Dc / 4;

    sc_table<<<(2048 * 64) / 256, 256>>>();
    convert_split<<<(N4 + 255) / 256, 256>>>(X, xh, xl, N4);
    convert_wt<<<dim3(64, 64, 4), dim3(32, 8)>>>(Wq, Wk, Wv, Wo, wh);

    const int GEMM_SMEM = 98304;   // 2 stages x (Ah 16K + Al 16K + B 16K)
    cudaFuncSetAttribute(gemm_mma, cudaFuncAttributeMaxDynamicSharedMemorySize, GEMM_SMEM);
    // fused QKV: grid.z selects weight + output
    gemm_mma<<<dim3(16, 32, 3), 256, GEMM_SMEM>>>(xh, xl, wh, qp, kp, vp);

    rope_split<<<(Bc * Sc * Hc * 64) / 256, 256>>>(pos);
    vt_half<<<dim3(64, 4, 32), dim3(32, 8)>>>();

    const int FLASH_SMEM = 98304;   // Q 32KB + K 32KB + V 32KB
    cudaFuncSetAttribute(flash_mma, cudaFuncAttributeMaxDynamicSharedMemorySize, FLASH_SMEM);
    flash_mma<<<dim3(Sc / BQ, Hc, Bc), 128, FLASH_SMEM>>>(am);

    // Wo projection
    gemm_mma<<<dim3(16, 32, 1), 256, GEMM_SMEM>>>(xh, xl, wh + 3 * WSZ, out, out, out);
}